// round 15
// baseline (speedup 1.0000x reference)
#include <cuda_runtime.h>
#include <cuda_bf16.h>
#include <cstdint>

#define B_  16
#define T_  64
#define V_  32000
#define E_  256
#define H_  1024
#define G4  4096
#define BH  (B_*H_)
#define NBLK 128
#define NEGV (-1e9f)

typedef unsigned long long ull;

// ---------------- device scratch ----------------
__device__ float g_qemb[B_*T_*E_];
__device__ float g_remb[B_*T_*E_];
__device__ float g_zpre_enc[B_*T_*G4];
__device__ float g_zpre_dec[B_*T_*G4];
__device__ float g_hA[2*BH];
__device__ float g_attnA[2*BH];
__device__ float g_c[BH];
__device__ float g_q[BH];
__device__ float g_ctx[BH];
__device__ float g_mem[B_*T_*H_];
__device__ float g_keys[B_*T_*H_];
__device__ float g_dec_out[B_*T_*H_];
__device__ float g_scores[B_*T_];
__device__ __nv_bfloat16 g_Ahi[B_*T_*H_];
__device__ __nv_bfloat16 g_Alo[B_*T_*H_];
// transposed weights: Wt[col][k] (k-contiguous per column)
__device__ float g_Wenc_t[G4*H_];        // 16MB  (enc h-part: k 0..1023)
__device__ float g_Wdec_t[G4*2048];      // 32MB  (dec attn+h part: k 0..2047)
__device__ float g_Wq_t[H_*H_];          // 4MB
__device__ float g_Wa_t[H_*2048];        // 8MB
// barrier state
__device__ unsigned g_arrive[NBLK];
__device__ unsigned g_release;

// ---------------- math helpers ----------------
__device__ __forceinline__ float sigf(float x) {
    return 1.0f / (1.0f + __expf(-x));
}
__device__ __forceinline__ float tanh_fast(float x) {
    float ax = fabsf(x);
    float e  = __expf(2.0f * ax);
    float r  = 1.0f - 2.0f / (e + 1.0f);
    return copysignf(r, x);
}

// ---------------- packed f32x2 helpers ----------------
__device__ __forceinline__ ull pk2(float x) {
    ull v; asm("mov.b64 %0, {%1, %1};" : "=l"(v) : "f"(x)); return v;
}
__device__ __forceinline__ float2 upk(ull v) {
    float2 r; asm("mov.b64 {%0, %1}, %2;" : "=f"(r.x), "=f"(r.y) : "l"(v)); return r;
}
__device__ __forceinline__ void ffma2(ull& d, ull a, ull b) {
    asm("fma.rn.f32x2 %0, %1, %2, %0;" : "+l"(d) : "l"(a), "l"(b));
}

// ---------------- acquire/release flag ops ----------------
__device__ __forceinline__ void st_rel(unsigned* p, unsigned v) {
    asm volatile("st.release.gpu.b32 [%0], %1;" :: "l"(p), "r"(v) : "memory");
}
__device__ __forceinline__ unsigned ld_acq(const unsigned* p) {
    unsigned v;
    asm volatile("ld.acquire.gpu.b32 %0, [%1];" : "=r"(v) : "l"(p) : "memory");
    return v;
}

__device__ __forceinline__ void grid_barrier(int j, int tt, unsigned ep) {
    __syncthreads();
    if (j == 0) {
        if (tt < NBLK) {
            if (tt == 0) st_rel(&g_arrive[0], ep);
            while (ld_acq(&g_arrive[tt]) != ep) {}
        }
        __syncthreads();
        if (tt == 0) st_rel(&g_release, ep);
    } else {
        if (tt == 0) {
            st_rel(&g_arrive[j], ep);
            while (ld_acq(&g_release) != ep) {}
        }
    }
    __syncthreads();
}

// ---------------- mma/ldmatrix helpers ----------------
__device__ __forceinline__ void ldm_x4(uint32_t* r, uint32_t addr) {
    asm volatile("ldmatrix.sync.aligned.m8n8.x4.shared.b16 {%0,%1,%2,%3}, [%4];"
                 : "=r"(r[0]), "=r"(r[1]), "=r"(r[2]), "=r"(r[3]) : "r"(addr));
}
__device__ __forceinline__ void ldm_x4t(uint32_t* r, uint32_t addr) {
    asm volatile("ldmatrix.sync.aligned.m8n8.x4.trans.shared.b16 {%0,%1,%2,%3}, [%4];"
                 : "=r"(r[0]), "=r"(r[1]), "=r"(r[2]), "=r"(r[3]) : "r"(addr));
}
__device__ __forceinline__ void mma_bf16(float* d, const uint32_t* a,
                                         uint32_t b0, uint32_t b1) {
    asm volatile("mma.sync.aligned.m16n8k16.row.col.f32.bf16.bf16.f32 "
                 "{%0,%1,%2,%3}, {%4,%5,%6,%7}, {%8,%9}, {%0,%1,%2,%3};"
                 : "+f"(d[0]), "+f"(d[1]), "+f"(d[2]), "+f"(d[3])
                 : "r"(a[0]), "r"(a[1]), "r"(a[2]), "r"(a[3]), "r"(b0), "r"(b1));
}
__device__ __forceinline__ uint32_t pack_bf16x2(__nv_bfloat16 a, __nv_bfloat16 b) {
    return ((uint32_t)__bfloat16_as_ushort(b) << 16) | (uint32_t)__bfloat16_as_ushort(a);
}

// ---------------- K0: embedding gather + zero state + barrier reset -------
__global__ void k_init(const int* __restrict__ enc_in,
                       const int* __restrict__ dec_in,
                       const float* __restrict__ emb) {
    if (blockIdx.x == 0) {
        if (threadIdx.x < NBLK) g_arrive[threadIdx.x] = 0u;
        if (threadIdx.x == NBLK) g_release = 0u;
    }
    int i = blockIdx.x * 256 + threadIdx.x;
    const int NE = B_*T_*E_;
    if (i < NE) {
        int bt = i >> 8, e = i & 255;
        g_qemb[i] = emb[(size_t)enc_in[bt] * E_ + e];
    } else if (i < 2*NE) {
        int j = i - NE;
        int bt = j >> 8, e = j & 255;
        g_remb[j] = emb[(size_t)dec_in[bt] * E_ + e];
    } else {
        int j = i - 2*NE;
        if (j < 2*BH)            g_hA[j] = 0.f;
        else if (j < 3*BH)       g_c[j - 2*BH] = 0.f;
        else if (j < 5*BH)       g_attnA[j - 3*BH] = 0.f;
    }
}

// ---------------- weight transpose: Wt[col][k] = W[rowOff+k][col] ---------
// 32x32 tiles, 32x8 threads
__global__ void k_transp(const float* __restrict__ W, float* __restrict__ Wt,
                         int rowOff, int K, int N) {
    __shared__ float tile[32][33];
    int kb = blockIdx.y * 32, nb = blockIdx.x * 32;
    int tx = threadIdx.x, ty = threadIdx.y;
#pragma unroll
    for (int r = 0; r < 32; r += 8)
        tile[ty + r][tx] = W[(size_t)(rowOff + kb + ty + r) * N + nb + tx];
    __syncthreads();
#pragma unroll
    for (int r = 0; r < 32; r += 8)
        Wt[(size_t)(nb + ty + r) * K + kb + tx] = tile[tx][ty + r];
}

// ================= persistent encoder =================
// 128 blocks x 512 threads. Block j owns gate-matched cols {g*1024+j*8+hl}.
__global__ __launch_bounds__(512, 1) void k_encoder(const float* __restrict__ bias,
                                                    const int* __restrict__ enc_len) {
    extern __shared__ float dsm[];
    float* xs  = dsm;
    float* red = dsm + 16384;
    const int j  = blockIdx.x;
    const int tt = threadIdx.x;
    const int cl = tt & 31, ks = tt >> 5;
    const int g  = cl >> 3, hl = cl & 7;
    const int col = g*1024 + j*8 + hl;
    const float4* Wp4 = (const float4*)(g_Wenc_t + (size_t)col * H_ + ks*64);

    for (int t = 0; t < T_; t++) {
        const float* hbuf = g_hA + (t & 1)*BH;
#pragma unroll
        for (int r = 0; r < 4; r++) {
            int i = tt + r*512;
            int b = i & 15, k8 = i >> 4;
            const float4* src = (const float4*)(hbuf + b*H_ + k8*8);
            float4 v0 = __ldcg(src);
            float4 v1 = __ldcg(src + 1);
            float* dst = xs + (k8*8)*16 + b;
            dst[0]  = v0.x; dst[16] = v0.y; dst[32] = v0.z; dst[48] = v0.w;
            dst[64] = v1.x; dst[80] = v1.y; dst[96] = v1.z; dst[112] = v1.w;
        }
        __syncthreads();

        ull acc2[8];
#pragma unroll
        for (int p = 0; p < 8; p++) acc2[p] = 0ull;
        const ull* xp = (const ull*)xs + (ks*64)*8;
#pragma unroll
        for (int kb = 0; kb < 4; kb++) {
            float4 w4[4];
#pragma unroll
            for (int u = 0; u < 4; u++) w4[u] = Wp4[kb*4 + u];
            float w[16] = {w4[0].x, w4[0].y, w4[0].z, w4[0].w,
                           w4[1].x, w4[1].y, w4[1].z, w4[1].w,
                           w4[2].x, w4[2].y, w4[2].z, w4[2].w,
                           w4[3].x, w4[3].y, w4[3].z, w4[3].w};
#pragma unroll
            for (int u = 0; u < 16; u++) {
                ull wd = pk2(w[u]);
                const ull* x8 = xp + (kb*16+u)*8;
#pragma unroll
                for (int p = 0; p < 8; p++) ffma2(acc2[p], wd, x8[p]);
            }
        }
        __syncthreads();
#pragma unroll
        for (int p = 0; p < 8; p++) {
            float2 f = upk(acc2[p]);
            red[(2*p  )*512 + ks*32 + cl] = f.x;
            red[(2*p+1)*512 + ks*32 + cl] = f.y;
        }
        __syncthreads();

        if (tt < 128) {
            int hh = tt & 7, b = tt >> 3;
            int c0 = j*8 + hh;
            const float* zp = g_zpre_enc + (size_t)(b*T_ + t)*G4;
            float zi = zp[c0]        + bias[c0];
            float zj = zp[1024 + c0] + bias[1024 + c0];
            float zf = zp[2048 + c0] + bias[2048 + c0];
            float zo = zp[3072 + c0] + bias[3072 + c0];
#pragma unroll
            for (int s = 0; s < 16; s++) {
                const float* r = red + b*512 + s*32;
                zi += r[hh]; zj += r[8+hh]; zf += r[16+hh]; zo += r[24+hh];
            }
            int idx = b*H_ + c0;
            float cc = g_c[idx];
            float cn = cc * sigf(zf + 1.f) + sigf(zi)*tanh_fast(zj);
            float hn = tanh_fast(cn)*sigf(zo);
            bool valid = t < enc_len[b];
            if (valid) g_c[idx] = cn;
            float* hout = g_hA + ((t+1)&1)*BH;
            float hold = __ldcg(&hbuf[idx]);
            __stcg(&hout[idx], valid ? hn : hold);
            g_mem[(size_t)(b*T_ + t)*H_ + c0] = valid ? hn : 0.f;
        }
        grid_barrier(j, tt, (unsigned)(t + 1));
    }
}

// ================= persistent decoder =================
__global__ __launch_bounds__(512, 1) void k_decoder(
    const float* __restrict__ bias, const float* __restrict__ v_att,
    const int* __restrict__ enc_len, const int* __restrict__ dec_len) {
    extern __shared__ float dsm[];
    float* xs  = dsm;
    float* red = dsm + 32768;
    const int j  = blockIdx.x;
    const int tt = threadIdx.x;
    const int cl = tt & 31, ks = tt >> 5;
    const int g  = cl >> 3, hl = cl & 7;
    const int colA = g*1024 + j*8 + hl;
    const int cl8 = tt & 7, ks64 = tt >> 3;
    const int colB = j*8 + cl8;
    const int bD = j >> 3;
    const float4* WpA4 = (const float4*)(g_Wdec_t + (size_t)colA * 2048 + ks*128);
    const float4* WpB4 = (const float4*)(g_Wq_t  + (size_t)colB * H_  + ks64*16);
    const float4* WpE4 = (const float4*)(g_Wa_t  + (size_t)colB * 2048 + ks64*32);

    for (int t = 0; t < T_; t++) {
        const unsigned ep0 = 64u + 5u*(unsigned)t;
        const float* hbuf    = g_hA    + (t & 1)*BH;
        const float* attnbuf = g_attnA + (t & 1)*BH;
        float* h2buf         = g_hA    + ((t+1)&1)*BH;
        float* attn_nx       = g_attnA + ((t+1)&1)*BH;

        // ---- Phase A: z = [attn,h]@Wd + zpre + bias -> gates ----
        {
#pragma unroll
            for (int r = 0; r < 8; r++) {
                int i = tt + r*512;
                int b = i & 15, k8 = i >> 4;
                const float4* src = (k8 < 128)
                    ? (const float4*)(attnbuf + b*H_ + k8*8)
                    : (const float4*)(hbuf + b*H_ + (k8-128)*8);
                float4 v0 = __ldcg(src);
                float4 v1 = __ldcg(src + 1);
                float* dst = xs + (k8*8)*16 + b;
                dst[0]  = v0.x; dst[16] = v0.y; dst[32] = v0.z; dst[48] = v0.w;
                dst[64] = v1.x; dst[80] = v1.y; dst[96] = v1.z; dst[112] = v1.w;
            }
            __syncthreads();

            ull acc2[8];
#pragma unroll
            for (int p = 0; p < 8; p++) acc2[p] = 0ull;
            const ull* xp = (const ull*)xs + (ks*128)*8;
#pragma unroll
            for (int kb = 0; kb < 8; kb++) {
                float4 w4[4];
#pragma unroll
                for (int u = 0; u < 4; u++) w4[u] = WpA4[kb*4 + u];
                float w[16] = {w4[0].x, w4[0].y, w4[0].z, w4[0].w,
                               w4[1].x, w4[1].y, w4[1].z, w4[1].w,
                               w4[2].x, w4[2].y, w4[2].z, w4[2].w,
                               w4[3].x, w4[3].y, w4[3].z, w4[3].w};
#pragma unroll
                for (int u = 0; u < 16; u++) {
                    ull wd = pk2(w[u]);
                    const ull* x8 = xp + (kb*16+u)*8;
#pragma unroll
                    for (int p = 0; p < 8; p++) ffma2(acc2[p], wd, x8[p]);
                }
            }
            __syncthreads();
#pragma unroll
            for (int p = 0; p < 8; p++) {
                float2 f = upk(acc2[p]);
                red[(2*p  )*512 + ks*32 + cl] = f.x;
                red[(2*p+1)*512 + ks*32 + cl] = f.y;
            }
            __syncthreads();
            if (tt < 128) {
                int hh = tt & 7, b = tt >> 3;
                int c0 = j*8 + hh;
                const float* zp = g_zpre_dec + (size_t)(b*T_ + t)*G4;
                float zi = zp[c0]        + bias[c0];
                float zj = zp[1024 + c0] + bias[1024 + c0];
                float zf = zp[2048 + c0] + bias[2048 + c0];
                float zo = zp[3072 + c0] + bias[3072 + c0];
#pragma unroll
                for (int s = 0; s < 16; s++) {
                    const float* r = red + b*512 + s*32;
                    zi += r[hh]; zj += r[8+hh]; zf += r[16+hh]; zo += r[24+hh];
                }
                int idx = b*H_ + c0;
                float cc = g_c[idx];
                float cn = cc * sigf(zf + 1.f) + sigf(zi)*tanh_fast(zj);
                float hn = tanh_fast(cn)*sigf(zo);
                g_c[idx] = cn;
                __stcg(&h2buf[idx], hn);
            }
        }
        grid_barrier(j, tt, ep0 + 1);

        // ---- Phase B: query = h2 @ Wq ----
        {
#pragma unroll
            for (int r = 0; r < 4; r++) {
                int i = tt + r*512;
                int b = i & 15, k8 = i >> 4;
                const float4* src = (const float4*)(h2buf + b*H_ + k8*8);
                float4 v0 = __ldcg(src);
                float4 v1 = __ldcg(src + 1);
                float* dst = xs + (k8*8)*16 + b;
                dst[0]  = v0.x; dst[16] = v0.y; dst[32] = v0.z; dst[48] = v0.w;
                dst[64] = v1.x; dst[80] = v1.y; dst[96] = v1.z; dst[112] = v1.w;
            }
            __syncthreads();

            ull acc2[8];
#pragma unroll
            for (int p = 0; p < 8; p++) acc2[p] = 0ull;
            const ull* xp = (const ull*)xs + (ks64*16)*8;
            float4 w4[4];
#pragma unroll
            for (int u = 0; u < 4; u++) w4[u] = WpB4[u];
            float w[16] = {w4[0].x, w4[0].y, w4[0].z, w4[0].w,
                           w4[1].x, w4[1].y, w4[1].z, w4[1].w,
                           w4[2].x, w4[2].y, w4[2].z, w4[2].w,
                           w4[3].x, w4[3].y, w4[3].z, w4[3].w};
#pragma unroll
            for (int u = 0; u < 16; u++) {
                ull wd = pk2(w[u]);
                const ull* x8 = xp + u*8;
#pragma unroll
                for (int p = 0; p < 8; p++) ffma2(acc2[p], wd, x8[p]);
            }
            __syncthreads();
#pragma unroll
            for (int p = 0; p < 8; p++) {
                float2 f = upk(acc2[p]);
                red[(2*p  )*512 + ks64*8 + cl8] = f.x;
                red[(2*p+1)*512 + ks64*8 + cl8] = f.y;
            }
            __syncthreads();
            if (tt < 128) {
                int clq = tt & 7, b = tt >> 3;
                float q = 0.f;
#pragma unroll
                for (int s = 0; s < 64; s++) q += red[b*512 + s*8 + clq];
                __stcg(&g_q[b*H_ + j*8 + clq], q);
            }
        }
        grid_barrier(j, tt, ep0 + 2);

        // ---- Phase C: scores[bD][t2] = v . tanh(keys + q) ----
        {
            if (tt < 256) {
                float4 v = __ldcg((const float4*)(g_q + bD*H_) + tt);
                *(float4*)(xs + tt*4) = v;
            }
            __syncthreads();
            int w    = tt >> 5;
            int p    = w >> 1;
            int half = w & 1;
            int lane = tt & 31;
            int t2 = (j & 7)*8 + p;
            const float* kr = g_keys + (size_t)(bD*T_ + t2)*H_;
            float s = 0.f;
            int h0 = half*512 + lane;
#pragma unroll 4
            for (int h = h0; h < half*512 + 512; h += 32)
                s += tanh_fast(kr[h] + xs[h]) * v_att[h];
#pragma unroll
            for (int o = 16; o > 0; o >>= 1) s += __shfl_xor_sync(0xffffffffu, s, o);
            if (lane == 0) red[w] = s;
            __syncthreads();
            if (tt < 8) {
                float val = red[2*tt] + red[2*tt + 1];
                __stcg(&g_scores[bD*T_ + (j & 7)*8 + tt], val);
            }
        }
        grid_barrier(j, tt, ep0 + 3);

        // ---- Phase D: softmax + context ----
        {
            float* al = red;
            if (tt < 32) {
                int L = enc_len[bD];
                float s0 = (tt      < L) ? __ldcg(&g_scores[bD*T_ + tt])      : NEGV;
                float s1 = (tt + 32 < L) ? __ldcg(&g_scores[bD*T_ + tt + 32]) : NEGV;
                float m = fmaxf(s0, s1);
#pragma unroll
                for (int o = 16; o > 0; o >>= 1) m = fmaxf(m, __shfl_xor_sync(0xffffffffu, m, o));
                float e0 = __expf(s0 - m), e1 = __expf(s1 - m);
                float ss = e0 + e1;
#pragma unroll
                for (int o = 16; o > 0; o >>= 1) ss += __shfl_xor_sync(0xffffffffu, ss, o);
                float inv = 1.f / ss;
                al[tt] = e0 * inv; al[tt + 32] = e1 * inv;
            }
            __syncthreads();
            if (tt < 128) {
                int h = (j & 7)*128 + tt;
                const float* mb = g_mem + (size_t)bD*T_*H_ + h;
                float a = 0.f;
#pragma unroll
                for (int t2 = 0; t2 < T_; t2++) a += al[t2] * mb[(size_t)t2 * H_];
                __stcg(&g_ctx[bD*H_ + h], a);
            }
        }
        grid_barrier(j, tt, ep0 + 4);

        // ---- Phase E: attn2 = [h2, ctx] @ Wa + finish ----
        {
#pragma unroll
            for (int r = 0; r < 8; r++) {
                int i = tt + r*512;
                int b = i & 15, k8 = i >> 4;
                const float4* src = (k8 < 128)
                    ? (const float4*)(h2buf + b*H_ + k8*8)
                    : (const float4*)(g_ctx + b*H_ + (k8-128)*8);
                float4 v0 = __ldcg(src);
                float4 v1 = __ldcg(src + 1);
                float* dst = xs + (k8*8)*16 + b;
                dst[0]  = v0.x; dst[16] = v0.y; dst[32] = v0.z; dst[48] = v0.w;
                dst[64] = v1.x; dst[80] = v1.y; dst[96] = v1.z; dst[112] = v1.w;
            }
            __syncthreads();

            ull acc2[8];
#pragma unroll
            for (int p = 0; p < 8; p++) acc2[p] = 0ull;
            const ull* xp = (const ull*)xs + (ks64*32)*8;
#pragma unroll
            for (int kb = 0; kb < 2; kb++) {
                float4 w4[4];
#pragma unroll
                for (int u = 0; u < 4; u++) w4[u] = WpE4[kb*4 + u];
                float w[16] = {w4[0].x, w4[0].y, w4[0].z, w4[0].w,
                               w4[1].x, w4[1].y, w4[1].z, w4[1].w,
                               w4[2].x, w4[2].y, w4[2].z, w4[2].w,
                               w4[3].x, w4[3].y, w4[3].z, w4[3].w};
#pragma unroll
                for (int u = 0; u < 16; u++) {
                    ull wd = pk2(w[u]);
                    const ull* x8 = xp + (kb*16+u)*8;
#pragma unroll
                    for (int p = 0; p < 8; p++) ffma2(acc2[p], wd, x8[p]);
                }
            }
            __syncthreads();
#pragma unroll
            for (int p = 0; p < 8; p++) {
                float2 f = upk(acc2[p]);
                red[(2*p  )*512 + ks64*8 + cl8] = f.x;
                red[(2*p+1)*512 + ks64*8 + cl8] = f.y;
            }
            __syncthreads();
            if (tt < 128) {
                int cla = tt & 7, b = tt >> 3;
                float a = 0.f;
#pragma unroll
                for (int s = 0; s < 64; s++) a += red[b*512 + s*8 + cla];
                int hh = j*8 + cla;
                __stcg(&attn_nx[b*H_ + hh], a);
                g_dec_out[(size_t)(b*T_ + t)*H_ + hh] = (t < dec_len[b]) ? a : 0.f;
            }
        }
        grid_barrier(j, tt, ep0 + 5);
    }
}

// ---------------- FFMA2 SGEMM (keys + preprojections) ----------------
__global__ __launch_bounds__(256, 2) void sgemm128(int mode,
                                                   const float* __restrict__ Bm,
                                                   int N, int K) {
    const float* A; float* C;
    if (mode == 0)      { A = g_mem;  C = g_keys; }
    else if (mode == 2) { A = g_qemb; C = g_zpre_enc; }
    else                { A = g_remb; C = g_zpre_dec; }

    __shared__ __align__(16) float As[2][8][264];
    __shared__ __align__(16) float Bs[2][8][128];
    const int tid = threadIdx.x;
    const int m0 = blockIdx.y * 128, n0 = blockIdx.x * 128;
    const int tx = tid & 15, ty = tid >> 4;
    const int la_r = tid >> 1, la_c = (tid & 1) * 4;
    const int lb_r = tid >> 5, lb_c = (tid & 31) * 4;

    ull acc2[8][4];
#pragma unroll
    for (int i = 0; i < 8; i++) {
#pragma unroll
        for (int jp = 0; jp < 4; jp++) acc2[i][jp] = 0ull;
    }

    {
        float4 a4 = *(const float4*)(A  + (size_t)(m0 + la_r) * K + la_c);
        float4 b4 = *(const float4*)(Bm + (size_t)lb_r * N + n0 + lb_c);
        *(float2*)&As[0][la_c+0][2*la_r] = make_float2(a4.x, a4.x);
        *(float2*)&As[0][la_c+1][2*la_r] = make_float2(a4.y, a4.y);
        *(float2*)&As[0][la_c+2][2*la_r] = make_float2(a4.z, a4.z);
        *(float2*)&As[0][la_c+3][2*la_r] = make_float2(a4.w, a4.w);
        *(float4*)&Bs[0][lb_r][lb_c] = b4;
    }
    __syncthreads();

    const int nk = K / 8;
    for (int kt = 0; kt < nk; kt++) {
        const int cur = kt & 1;
        float4 a4n, b4n;
        const bool nx = (kt + 1) < nk;
        if (nx) {
            int kb = (kt + 1) * 8;
            a4n = *(const float4*)(A  + (size_t)(m0 + la_r) * K + kb + la_c);
            b4n = *(const float4*)(Bm + (size_t)(kb + lb_r) * N + n0 + lb_c);
        }
#pragma unroll
        for (int k = 0; k < 8; k++) {
            const ull* ap = (const ull*)&As[cur][k][0];
            const ull* bp = (const ull*)&Bs[cur][k][0];
            ull av[8], bv[4];
#pragma unroll
            for (int i = 0; i < 4; i++) {
                av[i]   = ap[ty*4 + i];
                av[4+i] = ap[64 + ty*4 + i];
            }
            bv[0] = bp[tx*2];      bv[1] = bp[tx*2 + 1];
            bv[2] = bp[32 + tx*2]; bv[3] = bp[32 + tx*2 + 1];
#pragma unroll
            for (int i = 0; i < 8; i++) {
#pragma unroll
                for (int jp = 0; jp < 4; jp++) ffma2(acc2[i][jp], av[i], bv[jp]);
            }
        }
        if (nx) {
            const int nxt = cur ^ 1;
            *(float2*)&As[nxt][la_c+0][2*la_r] = make_float2(a4n.x, a4n.x);
            *(float2*)&As[nxt][la_c+1][2*la_r] = make_float2(a4n.y, a4n.y);
            *(float2*)&As[nxt][la_c+2][2*la_r] = make_float2(a4n.z, a4n.z);
            *(float2*)&As[nxt][la_c+3][2*la_r] = make_float2(a4n.w, a4n.w);
            *(float4*)&Bs[nxt][lb_r][lb_c] = b4n;
            __syncthreads();
        }
    }

#pragma unroll
    for (int i = 0; i < 8; i++) {
        int r = m0 + ((i < 4) ? (ty*4 + i) : (64 + ty*4 + (i - 4)));
        float2 p0 = upk(acc2[i][0]), p1 = upk(acc2[i][1]);
        float2 p2 = upk(acc2[i][2]), p3 = upk(acc2[i][3]);
        float4 v0 = make_float4(p0.x, p0.y, p1.x, p1.y);
        float4 v1 = make_float4(p2.x, p2.y, p3.x, p3.y);
        *(float4*)(C + (size_t)r * N + n0 + tx*4)      = v0;
        *(float4*)(C + (size_t)r * N + n0 + 64 + tx*4) = v1;
    }
}

// ================= logits on tensor cores (bf16 hi/lo split) ==============
__global__ void k_splitA() {
    int i = blockIdx.x * 512 + threadIdx.x;
    float x = g_dec_out[i];
    __nv_bfloat16 h = __float2bfloat16(x);
    g_Ahi[i] = h;
    g_Alo[i] = __float2bfloat16(x - __bfloat162float(h));
}

__global__ __launch_bounds__(512, 1) void k_logits(const float* __restrict__ Wk,
                                                   float* __restrict__ C) {
    extern __shared__ char smbuf[];
    __nv_bfloat16* sAhi = (__nv_bfloat16*)(smbuf);
    __nv_bfloat16* sAlo = (__nv_bfloat16*)(smbuf + 24576);
    __nv_bfloat16* sWhi = (__nv_bfloat16*)(smbuf + 49152);
    __nv_bfloat16* sWlo = (__nv_bfloat16*)(smbuf + 57856);
    const int tid  = threadIdx.x;
    const int lane = tid & 31;
    const int warp = tid >> 5;
    const int wm = warp & 3;
    const int wn = warp >> 2;
    const int n0 = blockIdx.x * 128;
    const int m0 = blockIdx.y * 256;
    const int ar = tid >> 1;
    const int ac = (tid & 1) * 8;
    const int wr = tid >> 5;
    const int wc = (tid & 31) * 4;

    const uint32_t uAhi = (uint32_t)__cvta_generic_to_shared(sAhi);
    const uint32_t uAlo = (uint32_t)__cvta_generic_to_shared(sAlo);
    const uint32_t uWhi = (uint32_t)__cvta_generic_to_shared(sWhi);
    const uint32_t uWlo = (uint32_t)__cvta_generic_to_shared(sWlo);

    const int aRow  = lane & 15;
    const int aColB = (lane >> 4) * 16;

    float acc[4][4][4];
#pragma unroll
    for (int mt = 0; mt < 4; mt++) {
#pragma unroll
        for (int nt = 0; nt < 4; nt++) {
#pragma unroll
            for (int q = 0; q < 4; q++) acc[mt][nt][q] = 0.0f;
        }
    }

    {
        uint4 va = *(const uint4*)(g_Ahi + (size_t)(m0 + ar) * H_ + ac);
        uint4 vl = *(const uint4*)(g_Alo + (size_t)(m0 + ar) * H_ + ac);
        *(uint4*)(sAhi + ar * 24 + ac) = va;
        *(uint4*)(sAlo + ar * 24 + ac) = vl;
        float4 w4 = *(const float4*)(Wk + (size_t)wr * V_ + n0 + wc);
        __nv_bfloat16 h0 = __float2bfloat16(w4.x);
        __nv_bfloat16 h1 = __float2bfloat16(w4.y);
        __nv_bfloat16 h2 = __float2bfloat16(w4.z);
        __nv_bfloat16 h3 = __float2bfloat16(w4.w);
        __nv_bfloat16 l0 = __float2bfloat16(w4.x - __bfloat162float(h0));
        __nv_bfloat16 l1 = __float2bfloat16(w4.y - __bfloat162float(h1));
        __nv_bfloat16 l2 = __float2bfloat16(w4.z - __bfloat162float(h2));
        __nv_bfloat16 l3 = __float2bfloat16(w4.w - __bfloat162float(h3));
        *(uint32_t*)(sWhi + wr * 136 + wc)     = pack_bf16x2(h0, h1);
        *(uint32_t*)(sWhi + wr * 136 + wc + 2) = pack_bf16x2(h2, h3);
        *(uint32_t*)(sWlo + wr * 136 + wc)     = pack_bf16x2(l0, l1);
        *(uint32_t*)(sWlo + wr * 136 + wc + 2) = pack_bf16x2(l2, l3);
    }
    __syncthreads();

    for (int kt = 0; kt < 64; kt++) {
        const int buf = kt & 1;
        const bool has = (kt < 63);
        uint4 na, nl;
        float4 nw;
        if (has) {
            int kn = (kt + 1) * 16;
            na = *(const uint4*)(g_Ahi + (size_t)(m0 + ar) * H_ + kn + ac);
            nl = *(const uint4*)(g_Alo + (size_t)(m0 + ar) * H_ + kn + ac);
            nw = *(const float4*)(Wk + (size_t)(kn + wr) * V_ + n0 + wc);
        }

        uint32_t bhi[2][4];
        uint32_t blo[2][4];
#pragma unroll
        for (int ch = 0; ch < 2; ch++) {
            uint32_t off = (uint32_t)(((buf * 16 + aRow) * 136 + wn * 32 + ch * 16) * 2 + aColB);
            ldm_x4t(bhi[ch], uWhi + off);
            ldm_x4t(blo[ch], uWlo + off);
        }

#pragma unroll
        for (int mt = 0; mt < 4; mt++) {
            uint32_t ah[4];
            uint32_t al[4];
            uint32_t off = (uint32_t)(((buf * 256 + wm * 64 + mt * 16 + aRow) * 24) * 2 + aColB);
            ldm_x4(ah, uAhi + off);
            ldm_x4(al, uAlo + off);
#pragma unroll
            for (int nt = 0; nt < 4; nt++) {
                uint32_t b0 = bhi[nt >> 1][(nt & 1) * 2];
                uint32_t b1 = bhi[nt >> 1][(nt & 1) * 2 + 1];
                uint32_t c0 = blo[nt >> 1][(nt & 1) * 2];
                uint32_t c1 = blo[nt >> 1][(nt & 1) * 2 + 1];
                mma_bf16(acc[mt][nt], ah, b0, b1);
                mma_bf16(acc[mt][nt], al, b0, b1);
                mma_bf16(acc[mt][nt], ah, c0, c1);
            }
        }

        if (has) {
            const int nbuf = buf ^ 1;
            *(uint4*)(sAhi + (nbuf * 256 + ar) * 24 + ac) = na;
            *(uint4*)(sAlo + (nbuf * 256 + ar) * 24 + ac) = nl;
            __nv_bfloat16 h0 = __float2bfloat16(nw.x);
            __nv_bfloat16 h1 = __float2bfloat16(nw.y);
            __nv_bfloat16 h2 = __float2bfloat16(nw.z);
            __nv_bfloat16 h3 = __float2bfloat16(nw.w);
            __nv_bfloat16 l0 = __float2bfloat16(nw.x - __bfloat162float(h0));
            __nv_bfloat16 l1 = __float2bfloat16(nw.y - __bfloat162float(h1));
            __nv_bfloat16 l2 = __float2bfloat16(nw.z - __bfloat162float(h2));
            __nv_bfloat16 l3 = __float2bfloat16(nw.w - __bfloat162float(h3));
            *(uint32_t*)(sWhi + (nbuf * 16 + wr) * 136 + wc)     = pack_bf16x2(h0, h1);
            *(uint32_t*)(sWhi + (nbuf * 16 + wr) * 136 + wc + 2) = pack_bf16x2(h2, h3);
            *(uint32_t*)(sWlo + (nbuf * 16 + wr) * 136 + wc)     = pack_bf16x2(l0, l1);
            *(uint32_t*)(sWlo + (nbuf * 16 + wr) * 136 + wc + 2) = pack_bf16x2(l2, l3);
        }
        __syncthreads();
    }

#pragma unroll
    for (int mt = 0; mt < 4; mt++) {
        int row = m0 + wm * 64 + mt * 16 + (lane >> 2);
#pragma unroll
        for (int nt = 0; nt < 4; nt++) {
            int col = n0 + wn * 32 + nt * 8 + (lane & 3) * 2;
            *(float2*)(C + (size_t)row * V_ + col) =
                make_float2(acc[mt][nt][0], acc[mt][nt][1]);
            *(float2*)(C + (size_t)(row + 8) * V_ + col) =
                make_float2(acc[mt][nt][2], acc[mt][nt][3]);
        }
    }
}

// ------------------------------ launcher ----------------------------------
extern "C" void kernel_launch(void* const* d_in, const int* in_sizes, int n_in,
                              void* d_out, int out_size) {
    const int*   enc_in  = (const int*)  d_in[0];
    const int*   dec_in  = (const int*)  d_in[1];
    const int*   enc_len = (const int*)  d_in[2];
    const int*   dec_len = (const int*)  d_in[3];
    const float* emb     = (const float*)d_in[4];
    const float* enc_k   = (const float*)d_in[5];
    const float* enc_b   = (const float*)d_in[6];
    const float* dec_k   = (const float*)d_in[7];
    const float* dec_b   = (const float*)d_in[8];
    const float* Wm      = (const float*)d_in[9];
    const float* Wq      = (const float*)d_in[10];
    const float* v_att   = (const float*)d_in[11];
    const float* attn_k  = (const float*)d_in[12];
    const float* out_k   = (const float*)d_in[13];
    float* out = (float*)d_out;

    cudaFuncSetAttribute(k_logits,  cudaFuncAttributeMaxDynamicSharedMemorySize, 66560);
    cudaFuncSetAttribute(k_encoder, cudaFuncAttributeMaxDynamicSharedMemorySize, 98304);
    cudaFuncSetAttribute(k_decoder, cudaFuncAttributeMaxDynamicSharedMemorySize, 163840);

    // resolve device scratch addresses for transposes
    float *dWenc, *dWdec, *dWq, *dWa;
    cudaGetSymbolAddress((void**)&dWenc, g_Wenc_t);
    cudaGetSymbolAddress((void**)&dWdec, g_Wdec_t);
    cudaGetSymbolAddress((void**)&dWq,   g_Wq_t);
    cudaGetSymbolAddress((void**)&dWa,   g_Wa_t);

    // embeddings + zero state + barrier reset
    k_init<<<2368, 256>>>(enc_in, dec_in, emb);

    // weight transposes (one-time per launch)
    k_transp<<<dim3(128, 32), dim3(32, 8)>>>(enc_k,  dWenc, E_, H_,   G4);
    k_transp<<<dim3(128, 64), dim3(32, 8)>>>(dec_k,  dWdec, E_, 2048, G4);
    k_transp<<<dim3(32, 32),  dim3(32, 8)>>>(Wq,     dWq,   0,  H_,   H_);
    k_transp<<<dim3(32, 64),  dim3(32, 8)>>>(attn_k, dWa,   0,  2048, H_);

    // precompute input projections for all timesteps
    sgemm128<<<dim3(32, 8), 256>>>(2, enc_k, G4, E_);
    sgemm128<<<dim3(32, 8), 256>>>(3, dec_k, G4, E_);

    // persistent encoder
    k_encoder<<<NBLK, 512, 98304>>>(enc_b, enc_len);

    // keys = memory @ Wm
    sgemm128<<<dim3(8, 8), 256>>>(0, Wm, H_, H_);

    // persistent decoder
    k_decoder<<<NBLK, 512, 163840>>>(dec_b, v_att, enc_len, dec_len);

    // logits on tensor cores
    k_splitA<<<2048, 512>>>();
    k_logits<<<dim3(250, 4), 512, 66560>>>(out_k, out);
}

// round 16
// speedup vs baseline: 1.1597x; 1.1597x over previous
#include <cuda_runtime.h>
#include <cuda_bf16.h>
#include <cstdint>

#define B_  16
#define T_  64
#define V_  32000
#define E_  256
#define H_  1024
#define G4  4096
#define BH  (B_*H_)
#define NBLK 128
#define NEGV (-1e9f)

typedef unsigned long long ull;

// ---------------- device scratch ----------------
__device__ float g_qemb[B_*T_*E_];
__device__ float g_remb[B_*T_*E_];
__device__ float g_zpre_enc[B_*T_*G4];
__device__ float g_zpre_dec[B_*T_*G4];
__device__ float g_hA[2*BH];
__device__ float g_attnA[2*BH];
__device__ float g_c[BH];
__device__ float g_q[BH];
__device__ float g_ctx[BH];
__device__ float g_mem[B_*T_*H_];
__device__ float g_keys[B_*T_*H_];
__device__ float g_dec_out[B_*T_*H_];
__device__ float g_scores[B_*T_];
__device__ __nv_bfloat16 g_Ahi[B_*T_*H_];
__device__ __nv_bfloat16 g_Alo[B_*T_*H_];
// barrier state
__device__ unsigned g_arrive[NBLK];
__device__ unsigned g_release;

// ---------------- math helpers ----------------
__device__ __forceinline__ float sigf(float x) {
    return 1.0f / (1.0f + __expf(-x));
}
__device__ __forceinline__ float tanh_fast(float x) {
    float ax = fabsf(x);
    float e  = __expf(2.0f * ax);
    float r  = 1.0f - 2.0f / (e + 1.0f);
    return copysignf(r, x);
}

// ---------------- packed f32x2 helpers ----------------
__device__ __forceinline__ ull pk2(float x) {
    ull v; asm("mov.b64 %0, {%1, %1};" : "=l"(v) : "f"(x)); return v;
}
__device__ __forceinline__ float2 upk(ull v) {
    float2 r; asm("mov.b64 {%0, %1}, %2;" : "=f"(r.x), "=f"(r.y) : "l"(v)); return r;
}
__device__ __forceinline__ void ffma2(ull& d, ull a, ull b) {
    asm("fma.rn.f32x2 %0, %1, %2, %0;" : "+l"(d) : "l"(a), "l"(b));
}

// ---------------- acquire/release flag ops ----------------
__device__ __forceinline__ void st_rel(unsigned* p, unsigned v) {
    asm volatile("st.release.gpu.b32 [%0], %1;" :: "l"(p), "r"(v) : "memory");
}
__device__ __forceinline__ unsigned ld_acq(const unsigned* p) {
    unsigned v;
    asm volatile("ld.acquire.gpu.b32 %0, [%1];" : "=r"(v) : "l"(p) : "memory");
    return v;
}

__device__ __forceinline__ void grid_barrier(int j, int tt, unsigned ep) {
    __syncthreads();
    if (j == 0) {
        if (tt < NBLK) {
            if (tt == 0) st_rel(&g_arrive[0], ep);
            while (ld_acq(&g_arrive[tt]) != ep) {}
        }
        __syncthreads();
        if (tt == 0) st_rel(&g_release, ep);
    } else {
        if (tt == 0) {
            st_rel(&g_arrive[j], ep);
            while (ld_acq(&g_release) != ep) {}
        }
    }
    __syncthreads();
}

// ---------------- mma/ldmatrix helpers ----------------
__device__ __forceinline__ void ldm_x4(uint32_t* r, uint32_t addr) {
    asm volatile("ldmatrix.sync.aligned.m8n8.x4.shared.b16 {%0,%1,%2,%3}, [%4];"
                 : "=r"(r[0]), "=r"(r[1]), "=r"(r[2]), "=r"(r[3]) : "r"(addr));
}
__device__ __forceinline__ void ldm_x4t(uint32_t* r, uint32_t addr) {
    asm volatile("ldmatrix.sync.aligned.m8n8.x4.trans.shared.b16 {%0,%1,%2,%3}, [%4];"
                 : "=r"(r[0]), "=r"(r[1]), "=r"(r[2]), "=r"(r[3]) : "r"(addr));
}
__device__ __forceinline__ void mma_bf16(float* d, const uint32_t* a,
                                         uint32_t b0, uint32_t b1) {
    asm volatile("mma.sync.aligned.m16n8k16.row.col.f32.bf16.bf16.f32 "
                 "{%0,%1,%2,%3}, {%4,%5,%6,%7}, {%8,%9}, {%0,%1,%2,%3};"
                 : "+f"(d[0]), "+f"(d[1]), "+f"(d[2]), "+f"(d[3])
                 : "r"(a[0]), "r"(a[1]), "r"(a[2]), "r"(a[3]), "r"(b0), "r"(b1));
}
__device__ __forceinline__ uint32_t pack_bf16x2(__nv_bfloat16 a, __nv_bfloat16 b) {
    return ((uint32_t)__bfloat16_as_ushort(b) << 16) | (uint32_t)__bfloat16_as_ushort(a);
}

// ---------------- K0: embedding gather + zero state + barrier reset -------
__global__ void k_init(const int* __restrict__ enc_in,
                       const int* __restrict__ dec_in,
                       const float* __restrict__ emb) {
    if (blockIdx.x == 0) {
        if (threadIdx.x < NBLK) g_arrive[threadIdx.x] = 0u;
        if (threadIdx.x == NBLK) g_release = 0u;
    }
    int i = blockIdx.x * 256 + threadIdx.x;
    const int NE = B_*T_*E_;
    if (i < NE) {
        int bt = i >> 8, e = i & 255;
        g_qemb[i] = emb[(size_t)enc_in[bt] * E_ + e];
    } else if (i < 2*NE) {
        int j = i - NE;
        int bt = j >> 8, e = j & 255;
        g_remb[j] = emb[(size_t)dec_in[bt] * E_ + e];
    } else {
        int j = i - 2*NE;
        if (j < 2*BH)            g_hA[j] = 0.f;
        else if (j < 3*BH)       g_c[j - 2*BH] = 0.f;
        else if (j < 5*BH)       g_attnA[j - 3*BH] = 0.f;
    }
}

// ================= persistent encoder =================
// 128 blocks x 512 threads. Block j owns gate-matched cols {g*1024+j*8+hl}.
__global__ __launch_bounds__(512, 1) void k_encoder(const float* __restrict__ W,
                                                    const float* __restrict__ bias,
                                                    const int* __restrict__ enc_len) {
    extern __shared__ float dsm[];
    float* xs  = dsm;
    float* red = dsm + 16384;
    const int j  = blockIdx.x;
    const int tt = threadIdx.x;
    const int cl = tt & 31, ks = tt >> 5;
    const int g  = cl >> 3, hl = cl & 7;
    const int col = g*1024 + j*8 + hl;
    const float* Wcol = W + (size_t)E_ * G4 + col;

    for (int t = 0; t < T_; t++) {
        const float* hbuf = g_hA + (t & 1)*BH;
#pragma unroll
        for (int r = 0; r < 4; r++) {
            int i = tt + r*512;
            int b = i & 15, k8 = i >> 4;
            const float4* src = (const float4*)(hbuf + b*H_ + k8*8);
            float4 v0 = __ldcg(src);
            float4 v1 = __ldcg(src + 1);
            float* dst = xs + (k8*8)*16 + b;
            dst[0]  = v0.x; dst[16] = v0.y; dst[32] = v0.z; dst[48] = v0.w;
            dst[64] = v1.x; dst[80] = v1.y; dst[96] = v1.z; dst[112] = v1.w;
        }
        __syncthreads();

        ull acc2[8];
#pragma unroll
        for (int p = 0; p < 8; p++) acc2[p] = 0ull;
        const float* Wp = Wcol + (size_t)(ks*64) * G4;
        const ulonglong2* xq = (const ulonglong2*)xs + (ks*64)*4;
#pragma unroll
        for (int kb = 0; kb < 4; kb++) {
            float w[16];
#pragma unroll
            for (int u = 0; u < 16; u++) w[u] = Wp[(size_t)(kb*16+u) * G4];
#pragma unroll
            for (int u = 0; u < 16; u++) {
                ull wd = pk2(w[u]);
                ulonglong2 x0 = xq[(kb*16+u)*4 + 0];
                ulonglong2 x1 = xq[(kb*16+u)*4 + 1];
                ulonglong2 x2 = xq[(kb*16+u)*4 + 2];
                ulonglong2 x3 = xq[(kb*16+u)*4 + 3];
                ffma2(acc2[0], wd, x0.x); ffma2(acc2[1], wd, x0.y);
                ffma2(acc2[2], wd, x1.x); ffma2(acc2[3], wd, x1.y);
                ffma2(acc2[4], wd, x2.x); ffma2(acc2[5], wd, x2.y);
                ffma2(acc2[6], wd, x3.x); ffma2(acc2[7], wd, x3.y);
            }
        }
        __syncthreads();
#pragma unroll
        for (int p = 0; p < 8; p++) {
            float2 f = upk(acc2[p]);
            red[(2*p  )*512 + ks*32 + cl] = f.x;
            red[(2*p+1)*512 + ks*32 + cl] = f.y;
        }
        __syncthreads();
        // parallel partial-sum: 512 threads each sum 16 slices (conflict-free)
        {
            int rb = tt >> 5, rc = tt & 31;
            float s = 0.f;
#pragma unroll
            for (int si = 0; si < 16; si++) s += red[rb*512 + si*32 + rc];
            xs[tt] = s;
        }
        __syncthreads();

        if (tt < 128) {
            int hh = tt & 7, b = tt >> 3;
            int c0 = j*8 + hh;
            const float* zp = g_zpre_enc + (size_t)(b*T_ + t)*G4;
            float zi = zp[c0]        + bias[c0]        + xs[b*32 + hh];
            float zj = zp[1024 + c0] + bias[1024 + c0] + xs[b*32 + 8 + hh];
            float zf = zp[2048 + c0] + bias[2048 + c0] + xs[b*32 + 16 + hh];
            float zo = zp[3072 + c0] + bias[3072 + c0] + xs[b*32 + 24 + hh];
            int idx = b*H_ + c0;
            float cc = g_c[idx];
            float cn = cc * sigf(zf + 1.f) + sigf(zi)*tanh_fast(zj);
            float hn = tanh_fast(cn)*sigf(zo);
            bool valid = t < enc_len[b];
            if (valid) g_c[idx] = cn;
            float* hout = g_hA + ((t+1)&1)*BH;
            float hold = __ldcg(&hbuf[idx]);
            __stcg(&hout[idx], valid ? hn : hold);
            g_mem[(size_t)(b*T_ + t)*H_ + c0] = valid ? hn : 0.f;
        }
        grid_barrier(j, tt, (unsigned)(t + 1));
    }
}

// ================= persistent decoder =================
__global__ __launch_bounds__(512, 1) void k_decoder(
    const float* __restrict__ Wd, const float* __restrict__ bias,
    const float* __restrict__ Wq, const float* __restrict__ v_att,
    const float* __restrict__ Wa,
    const int* __restrict__ enc_len, const int* __restrict__ dec_len) {
    extern __shared__ float dsm[];
    float* xs  = dsm;
    float* red = dsm + 32768;
    const int j  = blockIdx.x;
    const int tt = threadIdx.x;
    const int cl = tt & 31, ks = tt >> 5;
    const int g  = cl >> 3, hl = cl & 7;
    const int colA = g*1024 + j*8 + hl;
    const int cl8 = tt & 7, ks64 = tt >> 3;
    const int colB = j*8 + cl8;
    const int bD = j >> 3;

    for (int t = 0; t < T_; t++) {
        const unsigned ep0 = 64u + 5u*(unsigned)t;
        const float* hbuf    = g_hA    + (t & 1)*BH;
        const float* attnbuf = g_attnA + (t & 1)*BH;
        float* h2buf         = g_hA    + ((t+1)&1)*BH;
        float* attn_nx       = g_attnA + ((t+1)&1)*BH;

        // ---- Phase A: z = [attn,h]@Wd + zpre + bias -> gates ----
        {
#pragma unroll
            for (int r = 0; r < 8; r++) {
                int i = tt + r*512;
                int b = i & 15, k8 = i >> 4;
                const float4* src = (k8 < 128)
                    ? (const float4*)(attnbuf + b*H_ + k8*8)
                    : (const float4*)(hbuf + b*H_ + (k8-128)*8);
                float4 v0 = __ldcg(src);
                float4 v1 = __ldcg(src + 1);
                float* dst = xs + (k8*8)*16 + b;
                dst[0]  = v0.x; dst[16] = v0.y; dst[32] = v0.z; dst[48] = v0.w;
                dst[64] = v1.x; dst[80] = v1.y; dst[96] = v1.z; dst[112] = v1.w;
            }
            __syncthreads();

            ull acc2[8];
#pragma unroll
            for (int p = 0; p < 8; p++) acc2[p] = 0ull;
            const float* Wp = Wd + (size_t)(E_ + ks*128) * G4 + colA;
            const ulonglong2* xq = (const ulonglong2*)xs + (ks*128)*4;
#pragma unroll
            for (int kb = 0; kb < 8; kb++) {
                float w[16];
#pragma unroll
                for (int u = 0; u < 16; u++) w[u] = Wp[(size_t)(kb*16+u) * G4];
#pragma unroll
                for (int u = 0; u < 16; u++) {
                    ull wd = pk2(w[u]);
                    ulonglong2 x0 = xq[(kb*16+u)*4 + 0];
                    ulonglong2 x1 = xq[(kb*16+u)*4 + 1];
                    ulonglong2 x2 = xq[(kb*16+u)*4 + 2];
                    ulonglong2 x3 = xq[(kb*16+u)*4 + 3];
                    ffma2(acc2[0], wd, x0.x); ffma2(acc2[1], wd, x0.y);
                    ffma2(acc2[2], wd, x1.x); ffma2(acc2[3], wd, x1.y);
                    ffma2(acc2[4], wd, x2.x); ffma2(acc2[5], wd, x2.y);
                    ffma2(acc2[6], wd, x3.x); ffma2(acc2[7], wd, x3.y);
                }
            }
            __syncthreads();
#pragma unroll
            for (int p = 0; p < 8; p++) {
                float2 f = upk(acc2[p]);
                red[(2*p  )*512 + ks*32 + cl] = f.x;
                red[(2*p+1)*512 + ks*32 + cl] = f.y;
            }
            __syncthreads();
            {
                int rb = tt >> 5, rc = tt & 31;
                float s = 0.f;
#pragma unroll
                for (int si = 0; si < 16; si++) s += red[rb*512 + si*32 + rc];
                xs[tt] = s;
            }
            __syncthreads();
            if (tt < 128) {
                int hh = tt & 7, b = tt >> 3;
                int c0 = j*8 + hh;
                const float* zp = g_zpre_dec + (size_t)(b*T_ + t)*G4;
                float zi = zp[c0]        + bias[c0]        + xs[b*32 + hh];
                float zj = zp[1024 + c0] + bias[1024 + c0] + xs[b*32 + 8 + hh];
                float zf = zp[2048 + c0] + bias[2048 + c0] + xs[b*32 + 16 + hh];
                float zo = zp[3072 + c0] + bias[3072 + c0] + xs[b*32 + 24 + hh];
                int idx = b*H_ + c0;
                float cc = g_c[idx];
                float cn = cc * sigf(zf + 1.f) + sigf(zi)*tanh_fast(zj);
                float hn = tanh_fast(cn)*sigf(zo);
                g_c[idx] = cn;
                __stcg(&h2buf[idx], hn);
            }
        }
        grid_barrier(j, tt, ep0 + 1);

        // ---- Phase B: query = h2 @ Wq ----
        {
#pragma unroll
            for (int r = 0; r < 4; r++) {
                int i = tt + r*512;
                int b = i & 15, k8 = i >> 4;
                const float4* src = (const float4*)(h2buf + b*H_ + k8*8);
                float4 v0 = __ldcg(src);
                float4 v1 = __ldcg(src + 1);
                float* dst = xs + (k8*8)*16 + b;
                dst[0]  = v0.x; dst[16] = v0.y; dst[32] = v0.z; dst[48] = v0.w;
                dst[64] = v1.x; dst[80] = v1.y; dst[96] = v1.z; dst[112] = v1.w;
            }
            __syncthreads();

            ull acc2[8];
#pragma unroll
            for (int p = 0; p < 8; p++) acc2[p] = 0ull;
            const float* Wp = Wq + (size_t)(ks64*16) * H_ + colB;
            const ulonglong2* xq = (const ulonglong2*)xs + (ks64*16)*4;
            float w[16];
#pragma unroll
            for (int u = 0; u < 16; u++) w[u] = Wp[(size_t)u * H_];
#pragma unroll
            for (int u = 0; u < 16; u++) {
                ull wd = pk2(w[u]);
                ulonglong2 x0 = xq[u*4 + 0];
                ulonglong2 x1 = xq[u*4 + 1];
                ulonglong2 x2 = xq[u*4 + 2];
                ulonglong2 x3 = xq[u*4 + 3];
                ffma2(acc2[0], wd, x0.x); ffma2(acc2[1], wd, x0.y);
                ffma2(acc2[2], wd, x1.x); ffma2(acc2[3], wd, x1.y);
                ffma2(acc2[4], wd, x2.x); ffma2(acc2[5], wd, x2.y);
                ffma2(acc2[6], wd, x3.x); ffma2(acc2[7], wd, x3.y);
            }
            __syncthreads();
#pragma unroll
            for (int p = 0; p < 8; p++) {
                float2 f = upk(acc2[p]);
                red[(2*p  )*512 + ks64*8 + cl8] = f.x;
                red[(2*p+1)*512 + ks64*8 + cl8] = f.y;
            }
            __syncthreads();
            {
                int rb = tt >> 5, rem = tt & 31, rq = rem >> 3, rc = rem & 7;
                float s = 0.f;
#pragma unroll
                for (int i = 0; i < 16; i++) {
                    int si = rq + i*4;
                    s += red[rb*512 + si*8 + rc];
                }
                xs[tt] = s;
            }
            __syncthreads();
            if (tt < 128) {
                int clq = tt & 7, b = tt >> 3;
                float q = xs[b*32 + clq] + xs[b*32 + 8 + clq]
                        + xs[b*32 + 16 + clq] + xs[b*32 + 24 + clq];
                __stcg(&g_q[b*H_ + j*8 + clq], q);
            }
        }
        grid_barrier(j, tt, ep0 + 2);

        // ---- Phase C: scores[bD][t2] = v . tanh(keys + q) ----
        {
            if (tt < 256) {
                float4 v = __ldcg((const float4*)(g_q + bD*H_) + tt);
                *(float4*)(xs + tt*4) = v;
            }
            __syncthreads();
            int w    = tt >> 5;
            int p    = w >> 1;
            int half = w & 1;
            int lane = tt & 31;
            int t2 = (j & 7)*8 + p;
            const float* kr = g_keys + (size_t)(bD*T_ + t2)*H_;
            float s = 0.f;
            int h0 = half*512 + lane;
#pragma unroll 4
            for (int h = h0; h < half*512 + 512; h += 32)
                s += tanh_fast(kr[h] + xs[h]) * v_att[h];
#pragma unroll
            for (int o = 16; o > 0; o >>= 1) s += __shfl_xor_sync(0xffffffffu, s, o);
            if (lane == 0) red[w] = s;
            __syncthreads();
            if (tt < 8) {
                float val = red[2*tt] + red[2*tt + 1];
                __stcg(&g_scores[bD*T_ + (j & 7)*8 + tt], val);
            }
        }
        grid_barrier(j, tt, ep0 + 3);

        // ---- Phase D: softmax + context ----
        {
            float* al = red;
            if (tt < 32) {
                int L = enc_len[bD];
                float s0 = (tt      < L) ? __ldcg(&g_scores[bD*T_ + tt])      : NEGV;
                float s1 = (tt + 32 < L) ? __ldcg(&g_scores[bD*T_ + tt + 32]) : NEGV;
                float m = fmaxf(s0, s1);
#pragma unroll
                for (int o = 16; o > 0; o >>= 1) m = fmaxf(m, __shfl_xor_sync(0xffffffffu, m, o));
                float e0 = __expf(s0 - m), e1 = __expf(s1 - m);
                float ss = e0 + e1;
#pragma unroll
                for (int o = 16; o > 0; o >>= 1) ss += __shfl_xor_sync(0xffffffffu, ss, o);
                float inv = 1.f / ss;
                al[tt] = e0 * inv; al[tt + 32] = e1 * inv;
            }
            __syncthreads();
            if (tt < 128) {
                int h = (j & 7)*128 + tt;
                const float* mb = g_mem + (size_t)bD*T_*H_ + h;
                float a = 0.f;
#pragma unroll
                for (int t2 = 0; t2 < T_; t2++) a += al[t2] * mb[(size_t)t2 * H_];
                __stcg(&g_ctx[bD*H_ + h], a);
            }
        }
        grid_barrier(j, tt, ep0 + 4);

        // ---- Phase E: attn2 = [h2, ctx] @ Wa + finish ----
        {
#pragma unroll
            for (int r = 0; r < 8; r++) {
                int i = tt + r*512;
                int b = i & 15, k8 = i >> 4;
                const float4* src = (k8 < 128)
                    ? (const float4*)(h2buf + b*H_ + k8*8)
                    : (const float4*)(g_ctx + b*H_ + (k8-128)*8);
                float4 v0 = __ldcg(src);
                float4 v1 = __ldcg(src + 1);
                float* dst = xs + (k8*8)*16 + b;
                dst[0]  = v0.x; dst[16] = v0.y; dst[32] = v0.z; dst[48] = v0.w;
                dst[64] = v1.x; dst[80] = v1.y; dst[96] = v1.z; dst[112] = v1.w;
            }
            __syncthreads();

            ull acc2[8];
#pragma unroll
            for (int p = 0; p < 8; p++) acc2[p] = 0ull;
            const float* Wp = Wa + (size_t)(ks64*32) * H_ + colB;
            const ulonglong2* xq = (const ulonglong2*)xs + (ks64*32)*4;
#pragma unroll
            for (int kb = 0; kb < 2; kb++) {
                float w[16];
#pragma unroll
                for (int u = 0; u < 16; u++) w[u] = Wp[(size_t)(kb*16+u) * H_];
#pragma unroll
                for (int u = 0; u < 16; u++) {
                    ull wd = pk2(w[u]);
                    ulonglong2 x0 = xq[(kb*16+u)*4 + 0];
                    ulonglong2 x1 = xq[(kb*16+u)*4 + 1];
                    ulonglong2 x2 = xq[(kb*16+u)*4 + 2];
                    ulonglong2 x3 = xq[(kb*16+u)*4 + 3];
                    ffma2(acc2[0], wd, x0.x); ffma2(acc2[1], wd, x0.y);
                    ffma2(acc2[2], wd, x1.x); ffma2(acc2[3], wd, x1.y);
                    ffma2(acc2[4], wd, x2.x); ffma2(acc2[5], wd, x2.y);
                    ffma2(acc2[6], wd, x3.x); ffma2(acc2[7], wd, x3.y);
                }
            }
            __syncthreads();
#pragma unroll
            for (int p = 0; p < 8; p++) {
                float2 f = upk(acc2[p]);
                red[(2*p  )*512 + ks64*8 + cl8] = f.x;
                red[(2*p+1)*512 + ks64*8 + cl8] = f.y;
            }
            __syncthreads();
            {
                int rb = tt >> 5, rem = tt & 31, rq = rem >> 3, rc = rem & 7;
                float s = 0.f;
#pragma unroll
                for (int i = 0; i < 16; i++) {
                    int si = rq + i*4;
                    s += red[rb*512 + si*8 + rc];
                }
                xs[tt] = s;
            }
            __syncthreads();
            if (tt < 128) {
                int cla = tt & 7, b = tt >> 3;
                float a = xs[b*32 + cla] + xs[b*32 + 8 + cla]
                        + xs[b*32 + 16 + cla] + xs[b*32 + 24 + cla];
                int hh = j*8 + cla;
                __stcg(&attn_nx[b*H_ + hh], a);
                g_dec_out[(size_t)(b*T_ + t)*H_ + hh] = (t < dec_len[b]) ? a : 0.f;
            }
        }
        grid_barrier(j, tt, ep0 + 5);
    }
}

// ---------------- FFMA2 SGEMM (keys + preprojections) ----------------
__global__ __launch_bounds__(256, 2) void sgemm128(int mode,
                                                   const float* __restrict__ Bm,
                                                   int N, int K) {
    const float* A; float* C;
    if (mode == 0)      { A = g_mem;  C = g_keys; }
    else if (mode == 2) { A = g_qemb; C = g_zpre_enc; }
    else                { A = g_remb; C = g_zpre_dec; }

    __shared__ __align__(16) float As[2][8][264];
    __shared__ __align__(16) float Bs[2][8][128];
    const int tid = threadIdx.x;
    const int m0 = blockIdx.y * 128, n0 = blockIdx.x * 128;
    const int tx = tid & 15, ty = tid >> 4;
    const int la_r = tid >> 1, la_c = (tid & 1) * 4;
    const int lb_r = tid >> 5, lb_c = (tid & 31) * 4;

    ull acc2[8][4];
#pragma unroll
    for (int i = 0; i < 8; i++) {
#pragma unroll
        for (int jp = 0; jp < 4; jp++) acc2[i][jp] = 0ull;
    }

    {
        float4 a4 = *(const float4*)(A  + (size_t)(m0 + la_r) * K + la_c);
        float4 b4 = *(const float4*)(Bm + (size_t)lb_r * N + n0 + lb_c);
        *(float2*)&As[0][la_c+0][2*la_r] = make_float2(a4.x, a4.x);
        *(float2*)&As[0][la_c+1][2*la_r] = make_float2(a4.y, a4.y);
        *(float2*)&As[0][la_c+2][2*la_r] = make_float2(a4.z, a4.z);
        *(float2*)&As[0][la_c+3][2*la_r] = make_float2(a4.w, a4.w);
        *(float4*)&Bs[0][lb_r][lb_c] = b4;
    }
    __syncthreads();

    const int nk = K / 8;
    for (int kt = 0; kt < nk; kt++) {
        const int cur = kt & 1;
        float4 a4n, b4n;
        const bool nx = (kt + 1) < nk;
        if (nx) {
            int kb = (kt + 1) * 8;
            a4n = *(const float4*)(A  + (size_t)(m0 + la_r) * K + kb + la_c);
            b4n = *(const float4*)(Bm + (size_t)(kb + lb_r) * N + n0 + lb_c);
        }
#pragma unroll
        for (int k = 0; k < 8; k++) {
            const ull* ap = (const ull*)&As[cur][k][0];
            const ull* bp = (const ull*)&Bs[cur][k][0];
            ull av[8], bv[4];
#pragma unroll
            for (int i = 0; i < 4; i++) {
                av[i]   = ap[ty*4 + i];
                av[4+i] = ap[64 + ty*4 + i];
            }
            bv[0] = bp[tx*2];      bv[1] = bp[tx*2 + 1];
            bv[2] = bp[32 + tx*2]; bv[3] = bp[32 + tx*2 + 1];
#pragma unroll
            for (int i = 0; i < 8; i++) {
#pragma unroll
                for (int jp = 0; jp < 4; jp++) ffma2(acc2[i][jp], av[i], bv[jp]);
            }
        }
        if (nx) {
            const int nxt = cur ^ 1;
            *(float2*)&As[nxt][la_c+0][2*la_r] = make_float2(a4n.x, a4n.x);
            *(float2*)&As[nxt][la_c+1][2*la_r] = make_float2(a4n.y, a4n.y);
            *(float2*)&As[nxt][la_c+2][2*la_r] = make_float2(a4n.z, a4n.z);
            *(float2*)&As[nxt][la_c+3][2*la_r] = make_float2(a4n.w, a4n.w);
            *(float4*)&Bs[nxt][lb_r][lb_c] = b4n;
            __syncthreads();
        }
    }

#pragma unroll
    for (int i = 0; i < 8; i++) {
        int r = m0 + ((i < 4) ? (ty*4 + i) : (64 + ty*4 + (i - 4)));
        float2 p0 = upk(acc2[i][0]), p1 = upk(acc2[i][1]);
        float2 p2 = upk(acc2[i][2]), p3 = upk(acc2[i][3]);
        float4 v0 = make_float4(p0.x, p0.y, p1.x, p1.y);
        float4 v1 = make_float4(p2.x, p2.y, p3.x, p3.y);
        *(float4*)(C + (size_t)r * N + n0 + tx*4)      = v0;
        *(float4*)(C + (size_t)r * N + n0 + 64 + tx*4) = v1;
    }
}

// ================= logits on tensor cores (bf16 hi/lo split) ==============
__global__ void k_splitA() {
    int i = blockIdx.x * 512 + threadIdx.x;
    float x = g_dec_out[i];
    __nv_bfloat16 h = __float2bfloat16(x);
    g_Ahi[i] = h;
    g_Alo[i] = __float2bfloat16(x - __bfloat162float(h));
}

__global__ __launch_bounds__(512, 1) void k_logits(const float* __restrict__ Wk,
                                                   float* __restrict__ C) {
    extern __shared__ char smbuf[];
    __nv_bfloat16* sAhi = (__nv_bfloat16*)(smbuf);
    __nv_bfloat16* sAlo = (__nv_bfloat16*)(smbuf + 24576);
    __nv_bfloat16* sWhi = (__nv_bfloat16*)(smbuf + 49152);
    __nv_bfloat16* sWlo = (__nv_bfloat16*)(smbuf + 57856);
    const int tid  = threadIdx.x;
    const int lane = tid & 31;
    const int warp = tid >> 5;
    const int wm = warp & 3;
    const int wn = warp >> 2;
    const int n0 = blockIdx.x * 128;
    const int m0 = blockIdx.y * 256;
    const int ar = tid >> 1;
    const int ac = (tid & 1) * 8;
    const int wr = tid >> 5;
    const int wc = (tid & 31) * 4;

    const uint32_t uAhi = (uint32_t)__cvta_generic_to_shared(sAhi);
    const uint32_t uAlo = (uint32_t)__cvta_generic_to_shared(sAlo);
    const uint32_t uWhi = (uint32_t)__cvta_generic_to_shared(sWhi);
    const uint32_t uWlo = (uint32_t)__cvta_generic_to_shared(sWlo);

    const int aRow  = lane & 15;
    const int aColB = (lane >> 4) * 16;

    float acc[4][4][4];
#pragma unroll
    for (int mt = 0; mt < 4; mt++) {
#pragma unroll
        for (int nt = 0; nt < 4; nt++) {
#pragma unroll
            for (int q = 0; q < 4; q++) acc[mt][nt][q] = 0.0f;
        }
    }

    {
        uint4 va = *(const uint4*)(g_Ahi + (size_t)(m0 + ar) * H_ + ac);
        uint4 vl = *(const uint4*)(g_Alo + (size_t)(m0 + ar) * H_ + ac);
        *(uint4*)(sAhi + ar * 24 + ac) = va;
        *(uint4*)(sAlo + ar * 24 + ac) = vl;
        float4 w4 = *(const float4*)(Wk + (size_t)wr * V_ + n0 + wc);
        __nv_bfloat16 h0 = __float2bfloat16(w4.x);
        __nv_bfloat16 h1 = __float2bfloat16(w4.y);
        __nv_bfloat16 h2 = __float2bfloat16(w4.z);
        __nv_bfloat16 h3 = __float2bfloat16(w4.w);
        __nv_bfloat16 l0 = __float2bfloat16(w4.x - __bfloat162float(h0));
        __nv_bfloat16 l1 = __float2bfloat16(w4.y - __bfloat162float(h1));
        __nv_bfloat16 l2 = __float2bfloat16(w4.z - __bfloat162float(h2));
        __nv_bfloat16 l3 = __float2bfloat16(w4.w - __bfloat162float(h3));
        *(uint32_t*)(sWhi + wr * 136 + wc)     = pack_bf16x2(h0, h1);
        *(uint32_t*)(sWhi + wr * 136 + wc + 2) = pack_bf16x2(h2, h3);
        *(uint32_t*)(sWlo + wr * 136 + wc)     = pack_bf16x2(l0, l1);
        *(uint32_t*)(sWlo + wr * 136 + wc + 2) = pack_bf16x2(l2, l3);
    }
    __syncthreads();

    for (int kt = 0; kt < 64; kt++) {
        const int buf = kt & 1;
        const bool has = (kt < 63);
        uint4 na, nl;
        float4 nw;
        if (has) {
            int kn = (kt + 1) * 16;
            na = *(const uint4*)(g_Ahi + (size_t)(m0 + ar) * H_ + kn + ac);
            nl = *(const uint4*)(g_Alo + (size_t)(m0 + ar) * H_ + kn + ac);
            nw = *(const float4*)(Wk + (size_t)(kn + wr) * V_ + n0 + wc);
        }

        uint32_t bhi[2][4];
        uint32_t blo[2][4];
#pragma unroll
        for (int ch = 0; ch < 2; ch++) {
            uint32_t off = (uint32_t)(((buf * 16 + aRow) * 136 + wn * 32 + ch * 16) * 2 + aColB);
            ldm_x4t(bhi[ch], uWhi + off);
            ldm_x4t(blo[ch], uWlo + off);
        }

#pragma unroll
        for (int mt = 0; mt < 4; mt++) {
            uint32_t ah[4];
            uint32_t al[4];
            uint32_t off = (uint32_t)(((buf * 256 + wm * 64 + mt * 16 + aRow) * 24) * 2 + aColB);
            ldm_x4(ah, uAhi + off);
            ldm_x4(al, uAlo + off);
#pragma unroll
            for (int nt = 0; nt < 4; nt++) {
                uint32_t b0 = bhi[nt >> 1][(nt & 1) * 2];
                uint32_t b1 = bhi[nt >> 1][(nt & 1) * 2 + 1];
                uint32_t c0 = blo[nt >> 1][(nt & 1) * 2];
                uint32_t c1 = blo[nt >> 1][(nt & 1) * 2 + 1];
                mma_bf16(acc[mt][nt], ah, b0, b1);
                mma_bf16(acc[mt][nt], al, b0, b1);
                mma_bf16(acc[mt][nt], ah, c0, c1);
            }
        }

        if (has) {
            const int nbuf = buf ^ 1;
            *(uint4*)(sAhi + (nbuf * 256 + ar) * 24 + ac) = na;
            *(uint4*)(sAlo + (nbuf * 256 + ar) * 24 + ac) = nl;
            __nv_bfloat16 h0 = __float2bfloat16(nw.x);
            __nv_bfloat16 h1 = __float2bfloat16(nw.y);
            __nv_bfloat16 h2 = __float2bfloat16(nw.z);
            __nv_bfloat16 h3 = __float2bfloat16(nw.w);
            __nv_bfloat16 l0 = __float2bfloat16(nw.x - __bfloat162float(h0));
            __nv_bfloat16 l1 = __float2bfloat16(nw.y - __bfloat162float(h1));
            __nv_bfloat16 l2 = __float2bfloat16(nw.z - __bfloat162float(h2));
            __nv_bfloat16 l3 = __float2bfloat16(nw.w - __bfloat162float(h3));
            *(uint32_t*)(sWhi + (nbuf * 16 + wr) * 136 + wc)     = pack_bf16x2(h0, h1);
            *(uint32_t*)(sWhi + (nbuf * 16 + wr) * 136 + wc + 2) = pack_bf16x2(h2, h3);
            *(uint32_t*)(sWlo + (nbuf * 16 + wr) * 136 + wc)     = pack_bf16x2(l0, l1);
            *(uint32_t*)(sWlo + (nbuf * 16 + wr) * 136 + wc + 2) = pack_bf16x2(l2, l3);
        }
        __syncthreads();
    }

#pragma unroll
    for (int mt = 0; mt < 4; mt++) {
        int row = m0 + wm * 64 + mt * 16 + (lane >> 2);
#pragma unroll
        for (int nt = 0; nt < 4; nt++) {
            int col = n0 + wn * 32 + nt * 8 + (lane & 3) * 2;
            *(float2*)(C + (size_t)row * V_ + col) =
                make_float2(acc[mt][nt][0], acc[mt][nt][1]);
            *(float2*)(C + (size_t)(row + 8) * V_ + col) =
                make_float2(acc[mt][nt][2], acc[mt][nt][3]);
        }
    }
}

// ------------------------------ launcher ----------------------------------
extern "C" void kernel_launch(void* const* d_in, const int* in_sizes, int n_in,
                              void* d_out, int out_size) {
    const int*   enc_in  = (const int*)  d_in[0];
    const int*   dec_in  = (const int*)  d_in[1];
    const int*   enc_len = (const int*)  d_in[2];
    const int*   dec_len = (const int*)  d_in[3];
    const float* emb     = (const float*)d_in[4];
    const float* enc_k   = (const float*)d_in[5];
    const float* enc_b   = (const float*)d_in[6];
    const float* dec_k   = (const float*)d_in[7];
    const float* dec_b   = (const float*)d_in[8];
    const float* Wm      = (const float*)d_in[9];
    const float* Wq      = (const float*)d_in[10];
    const float* v_att   = (const float*)d_in[11];
    const float* attn_k  = (const float*)d_in[12];
    const float* out_k   = (const float*)d_in[13];
    float* out = (float*)d_out;

    cudaFuncSetAttribute(k_logits,  cudaFuncAttributeMaxDynamicSharedMemorySize, 66560);
    cudaFuncSetAttribute(k_encoder, cudaFuncAttributeMaxDynamicSharedMemorySize, 98304);
    cudaFuncSetAttribute(k_decoder, cudaFuncAttributeMaxDynamicSharedMemorySize, 163840);

    // embeddings + zero state + barrier reset
    k_init<<<2368, 256>>>(enc_in, dec_in, emb);

    // precompute input projections for all timesteps
    sgemm128<<<dim3(32, 8), 256>>>(2, enc_k, G4, E_);
    sgemm128<<<dim3(32, 8), 256>>>(3, dec_k, G4, E_);

    // persistent encoder
    k_encoder<<<NBLK, 512, 98304>>>(enc_k, enc_b, enc_len);

    // keys = memory @ Wm
    sgemm128<<<dim3(8, 8), 256>>>(0, Wm, H_, H_);

    // persistent decoder
    k_decoder<<<NBLK, 512, 163840>>>(dec_k, dec_b, Wq, v_att, attn_k,
                                     enc_len, dec_len);

    // logits on tensor cores
    k_splitA<<<2048, 512>>>();
    k_logits<<<dim3(250, 4), 512, 66560>>>(out_k, out);
}